// round 1
// baseline (speedup 1.0000x reference)
#include <cuda_runtime.h>
#include <math.h>

#define EMBED_DIM 512
#define NUM_HEADS 8
#define HEAD_DIM 64
#define T_LEN 128
#define BATCH 8
#define BH 64
#define SCALING 0.125f
#define LAMBDA 1.0f
#define TA 16   // a-rows per block in main kernel

// Scratch (allocation-free rule: __device__ globals)
__device__ float g_q[BH * T_LEN * HEAD_DIM];     // [i][t][hd], scaled
__device__ float g_k[BH * T_LEN * HEAD_DIM];
__device__ float g_v[BH * T_LEN * HEAD_DIM];
__device__ float g_attn2[T_LEN * BATCH * EMBED_DIM];  // [t][b][h*64+d]

// ---------------------------------------------------------------------------
// Kernel A: fused in-projection  out = X_s @ W_s^T + b_s  -> q/k/v [i][t][hd]
// Tiles: 128 rows (t*8+b) x 64 cols (j), K=512 in chunks of 16.
// ---------------------------------------------------------------------------
__global__ __launch_bounds__(256) void proj_in_kernel(
    const float* __restrict__ q_in, const float* __restrict__ k_in,
    const float* __restrict__ v_in, const float* __restrict__ W,
    const float* __restrict__ bias)
{
    const int jbase = blockIdx.x * 64;     // 0..1535
    const int rbase = blockIdx.y * 128;    // 0..1023
    const int section = jbase / 512;       // 0=q,1=k,2=v
    const float* __restrict__ X = (section == 0) ? q_in : (section == 1) ? k_in : v_in;

    __shared__ float Xs[16][128];
    __shared__ float Ws[16][64];

    const int tid = threadIdx.x;
    const int tx = tid & 15;        // 16 col-groups of 4
    const int ty = tid >> 4;        // 16 row-groups of 8

    float acc[8][4];
#pragma unroll
    for (int i = 0; i < 8; i++)
#pragma unroll
        for (int j = 0; j < 4; j++) acc[i][j] = 0.f;

    for (int k0 = 0; k0 < 512; k0 += 16) {
        // load X tile [128][16] transposed into Xs[kk][r]
#pragma unroll
        for (int rep = 0; rep < 2; rep++) {
            int lin = rep * 256 + tid;
            int r = lin >> 2;
            int kk = (lin & 3) * 4;
            float4 xv = *(const float4*)&X[(size_t)(rbase + r) * 512 + k0 + kk];
            Xs[kk + 0][r] = xv.x; Xs[kk + 1][r] = xv.y;
            Xs[kk + 2][r] = xv.z; Xs[kk + 3][r] = xv.w;
        }
        // load W tile [64][16] transposed into Ws[kk][j]
        {
            int j = tid >> 2;
            int kk = (tid & 3) * 4;
            float4 wv = *(const float4*)&W[(size_t)(jbase + j) * 512 + k0 + kk];
            Ws[kk + 0][j] = wv.x; Ws[kk + 1][j] = wv.y;
            Ws[kk + 2][j] = wv.z; Ws[kk + 3][j] = wv.w;
        }
        __syncthreads();
#pragma unroll
        for (int kk = 0; kk < 16; kk++) {
            float a0[8], b0[4];
            *(float4*)&a0[0] = *(float4*)&Xs[kk][ty * 8];
            *(float4*)&a0[4] = *(float4*)&Xs[kk][ty * 8 + 4];
            *(float4*)&b0[0] = *(float4*)&Ws[kk][tx * 4];
#pragma unroll
            for (int i = 0; i < 8; i++)
#pragma unroll
                for (int j = 0; j < 4; j++) acc[i][j] += a0[i] * b0[j];
        }
        __syncthreads();
    }

    float* dst = (section == 0) ? g_q : (section == 1) ? g_k : g_v;
#pragma unroll
    for (int i = 0; i < 8; i++) {
        int r = rbase + ty * 8 + i;
        int t = r >> 3;
        int bb = r & 7;
#pragma unroll
        for (int j = 0; j < 4; j++) {
            int jg = jbase + tx * 4 + j;
            float val = acc[i][j] + bias[jg];
            int jj = jg & 511;
            int h = jj >> 6;
            int dp = jj & 63;
            if (section == 0) val *= SCALING;
            dst[(((size_t)(bb * 8 + h)) * 128 + t) * 64 + dp] = val;
        }
    }
}

// ---------------------------------------------------------------------------
// Kernel B: main fused trilinear + bias + mean/max + softmax + attn bmm.
// Block = (head, a_tile, batch). For each a in tile:
//   X_a[b,c] = sum_t q[a,t]*k[b,t]*v[c,t]  (128x128x64 GEMM, registers)
//   s = X + bias;  fused[a,b] = mean_c(s) + max_c(s)
// Then softmax over b, attn[a,:] = sum_b w[a,b] q[b,:], write [t][b][h*64+d].
// ---------------------------------------------------------------------------
__global__ __launch_bounds__(256, 2) void tri_main_kernel(
    const float* __restrict__ cbias)
{
    const int head  = blockIdx.x;   // 0..7
    const int atile = blockIdx.y;   // 0..7
    const int batch = blockIdx.z;   // 0..7
    const int i = batch * 8 + head;

    const float* __restrict__ qi = g_q + (size_t)i * 8192;
    const float* __restrict__ ki = g_k + (size_t)i * 8192;
    const float* __restrict__ vi = g_v + (size_t)i * 8192;

    extern __shared__ float smem[];
    float* kT    = smem;             // [64][128] kT[t*128+b]
    float* vT    = smem + 8192;      // [64][128]
    float* qs    = smem + 16384;     // [16][64]
    float* fused = smem + 17408;     // [16][128]

    const int tid = threadIdx.x;
    const int tx = tid & 15;   // c groups
    const int ty = tid >> 4;   // b groups
    const int b0 = ty * 8;
    const int c0 = tx * 8;

    // transpose-load k, v into smem [t][pos]
    for (int idx = tid; idx < 8192; idx += 256) {
        int b = idx >> 6;
        int t = idx & 63;
        float kvk = ki[idx];
        float kvv = vi[idx];
        kT[t * 128 + b] = kvk;
        vT[t * 128 + b] = kvv;
    }
    for (int idx = tid; idx < TA * 64; idx += 256)
        qs[idx] = qi[atile * (TA * 64) + idx];
    __syncthreads();

    const float* __restrict__ bias_base =
        cbias + (size_t)batch * 128 * 128 * 128;

#pragma unroll 1
    for (int a = 0; a < TA; a++) {
        float acc[8][8];
#pragma unroll
        for (int x = 0; x < 8; x++)
#pragma unroll
            for (int y = 0; y < 8; y++) acc[x][y] = 0.f;

        const float* __restrict__ qrow = qs + a * 64;
#pragma unroll 4
        for (int t = 0; t < 64; t++) {
            float qa = qrow[t];
            float kf[8], vf[8];
            *(float4*)&kf[0] = *(const float4*)&kT[t * 128 + b0];
            *(float4*)&kf[4] = *(const float4*)&kT[t * 128 + b0 + 4];
            *(float4*)&vf[0] = *(const float4*)&vT[t * 128 + c0];
            *(float4*)&vf[4] = *(const float4*)&vT[t * 128 + c0 + 4];
            float pk[8];
#pragma unroll
            for (int x = 0; x < 8; x++) pk[x] = qa * kf[x];
#pragma unroll
            for (int x = 0; x < 8; x++)
#pragma unroll
                for (int y = 0; y < 8; y++) acc[x][y] += pk[x] * vf[y];
        }

        // bias add + per-row (b) sum/max over this thread's 8 c values
        const int ag = atile * TA + a;
        const float* __restrict__ bp =
            bias_base + (size_t)ag * 128 * 128;
        float rsum[8], rmax[8];
#pragma unroll
        for (int x = 0; x < 8; x++) {
            const float* row = bp + (size_t)(b0 + x) * 128 + c0;
            float4 bA = *(const float4*)&row[0];
            float4 bB = *(const float4*)&row[4];
            float s0 = acc[x][0] + LAMBDA * bA.x;
            float s1 = acc[x][1] + LAMBDA * bA.y;
            float s2 = acc[x][2] + LAMBDA * bA.z;
            float s3 = acc[x][3] + LAMBDA * bA.w;
            float s4 = acc[x][4] + LAMBDA * bB.x;
            float s5 = acc[x][5] + LAMBDA * bB.y;
            float s6 = acc[x][6] + LAMBDA * bB.z;
            float s7 = acc[x][7] + LAMBDA * bB.w;
            rsum[x] = ((s0 + s1) + (s2 + s3)) + ((s4 + s5) + (s6 + s7));
            float m01 = fmaxf(s0, s1), m23 = fmaxf(s2, s3);
            float m45 = fmaxf(s4, s5), m67 = fmaxf(s6, s7);
            rmax[x] = fmaxf(fmaxf(m01, m23), fmaxf(m45, m67));
        }
        // reduce across the 16 tx lanes (stays inside half-warp: offsets < 16)
#pragma unroll
        for (int off = 8; off >= 1; off >>= 1) {
#pragma unroll
            for (int x = 0; x < 8; x++) {
                rsum[x] += __shfl_xor_sync(0xffffffffu, rsum[x], off);
                rmax[x] = fmaxf(rmax[x], __shfl_xor_sync(0xffffffffu, rmax[x], off));
            }
        }
        if (tx == 0) {
#pragma unroll
            for (int x = 0; x < 8; x++)
                fused[a * 128 + b0 + x] = rsum[x] * (1.0f / 128.0f) + rmax[x];
        }
    }
    __syncthreads();

    // softmax over b for each row a (warp per row, 2 rows per warp)
    {
        int w = tid >> 5;
        int lane = tid & 31;
        for (int a = w; a < TA; a += 8) {
            float4 fv = *(float4*)&fused[a * 128 + lane * 4];
            float m = fmaxf(fmaxf(fv.x, fv.y), fmaxf(fv.z, fv.w));
#pragma unroll
            for (int off = 16; off >= 1; off >>= 1)
                m = fmaxf(m, __shfl_xor_sync(0xffffffffu, m, off));
            float e0 = __expf(fv.x - m), e1 = __expf(fv.y - m);
            float e2 = __expf(fv.z - m), e3 = __expf(fv.w - m);
            float s = (e0 + e1) + (e2 + e3);
#pragma unroll
            for (int off = 16; off >= 1; off >>= 1)
                s += __shfl_xor_sync(0xffffffffu, s, off);
            float inv = 1.0f / s;
            float4 ov = make_float4(e0 * inv, e1 * inv, e2 * inv, e3 * inv);
            *(float4*)&fused[a * 128 + lane * 4] = ov;
        }
    }
    __syncthreads();

    // attn[a, d0..d0+3] = sum_b w[a,b] * q[b, d0..]
    {
        int a = tid >> 4;            // 16 rows
        int d0 = (tid & 15) * 4;     // 64 cols
        float o0 = 0.f, o1 = 0.f, o2 = 0.f, o3 = 0.f;
        const float* wrow = fused + a * 128;
#pragma unroll 4
        for (int b = 0; b < 128; b++) {
            float wb = wrow[b];
            float4 qv = *(const float4*)&qi[b * 64 + d0];
            o0 += wb * qv.x; o1 += wb * qv.y;
            o2 += wb * qv.z; o3 += wb * qv.w;
        }
        int t = atile * TA + a;
        float* dst = g_attn2 + ((size_t)t * 8 + batch) * 512 + head * 64 + d0;
        *(float4*)dst = make_float4(o0, o1, o2, o3);
    }
}

// ---------------------------------------------------------------------------
// Kernel C: output projection  out[r][dd] = attn2[r][:] . out_w[dd][:] + out_b
// ---------------------------------------------------------------------------
__global__ __launch_bounds__(256) void proj_out_kernel(
    const float* __restrict__ W, const float* __restrict__ bias,
    float* __restrict__ out)
{
    const int jbase = blockIdx.x * 64;     // 0..511
    const int rbase = blockIdx.y * 128;    // 0..1023
    const float* __restrict__ X = g_attn2;

    __shared__ float Xs[16][128];
    __shared__ float Ws[16][64];

    const int tid = threadIdx.x;
    const int tx = tid & 15;
    const int ty = tid >> 4;

    float acc[8][4];
#pragma unroll
    for (int i = 0; i < 8; i++)
#pragma unroll
        for (int j = 0; j < 4; j++) acc[i][j] = 0.f;

    for (int k0 = 0; k0 < 512; k0 += 16) {
#pragma unroll
        for (int rep = 0; rep < 2; rep++) {
            int lin = rep * 256 + tid;
            int r = lin >> 2;
            int kk = (lin & 3) * 4;
            float4 xv = *(const float4*)&X[(size_t)(rbase + r) * 512 + k0 + kk];
            Xs[kk + 0][r] = xv.x; Xs[kk + 1][r] = xv.y;
            Xs[kk + 2][r] = xv.z; Xs[kk + 3][r] = xv.w;
        }
        {
            int j = tid >> 2;
            int kk = (tid & 3) * 4;
            float4 wv = *(const float4*)&W[(size_t)(jbase + j) * 512 + k0 + kk];
            Ws[kk + 0][j] = wv.x; Ws[kk + 1][j] = wv.y;
            Ws[kk + 2][j] = wv.z; Ws[kk + 3][j] = wv.w;
        }
        __syncthreads();
#pragma unroll
        for (int kk = 0; kk < 16; kk++) {
            float a0[8], b0[4];
            *(float4*)&a0[0] = *(float4*)&Xs[kk][ty * 8];
            *(float4*)&a0[4] = *(float4*)&Xs[kk][ty * 8 + 4];
            *(float4*)&b0[0] = *(float4*)&Ws[kk][tx * 4];
#pragma unroll
            for (int i = 0; i < 8; i++)
#pragma unroll
                for (int j = 0; j < 4; j++) acc[i][j] += a0[i] * b0[j];
        }
        __syncthreads();
    }

#pragma unroll
    for (int i = 0; i < 8; i++) {
        int r = rbase + ty * 8 + i;
#pragma unroll
        for (int j = 0; j < 4; j++) {
            int jg = jbase + tx * 4 + j;
            out[(size_t)r * 512 + jg] = acc[i][j] + bias[jg];
        }
    }
}

// ---------------------------------------------------------------------------
extern "C" void kernel_launch(void* const* d_in, const int* in_sizes, int n_in,
                              void* d_out, int out_size)
{
    const float* query = (const float*)d_in[0];   // [128,8,512]
    const float* key   = (const float*)d_in[1];
    const float* value = (const float*)d_in[2];
    const float* cbias = (const float*)d_in[3];   // [8,128,128,128]
    const float* ipw   = (const float*)d_in[4];   // [1536,512]
    const float* ipb   = (const float*)d_in[5];   // [1536]
    const float* outw  = (const float*)d_in[6];   // [512,512]
    const float* outb  = (const float*)d_in[7];   // [512]
    float* out = (float*)d_out;                   // [128,8,512]

    // in-projection: 24 col-tiles x 8 row-tiles
    proj_in_kernel<<<dim3(24, 8), 256>>>(query, key, value, ipw, ipb);

    // main fused kernel: needs >48KB dynamic smem
    static const size_t SMEM_B = (8192 + 8192 + TA * 64 + TA * 128) * sizeof(float);
    cudaFuncSetAttribute(tri_main_kernel,
                         cudaFuncAttributeMaxDynamicSharedMemorySize,
                         (int)SMEM_B);
    tri_main_kernel<<<dim3(8, 8, 8), 256, SMEM_B>>>(cbias);

    // out-projection
    proj_out_kernel<<<dim3(8, 8), 256>>>(outw, outb, out);
}